// round 6
// baseline (speedup 1.0000x reference)
#include <cuda_runtime.h>
#include <cuda_bf16.h>
#include <stdint.h>
#include <math.h>

typedef __nv_bfloat16 bf16;
typedef unsigned long long u64;
typedef unsigned int u32;

#define T_TOK 4096
#define HDIM  1024
#define IDIM  2048
#define NEXP  8
#define SLOTS (2 * T_TOK)

// ======================= scratch (device globals) =======================
// router path (bf16, high precision)
__device__ __align__(16) bf16 g_tch[(size_t)T_TOK * HDIM];
__device__ __align__(16) bf16 g_tcl[(size_t)T_TOK * HDIM];
__device__ __align__(16) bf16 g_tpwT_h[(size_t)HDIM * HDIM];
__device__ __align__(16) bf16 g_tpwT_l[(size_t)HDIM * HDIM];
__device__ float g_xr[(size_t)T_TOK * HDIM];

// int8 2-limb data
__device__ __align__(16) int8_t g_x8h[(size_t)T_TOK * HDIM];
__device__ __align__(16) int8_t g_x8l[(size_t)T_TOK * HDIM];
__device__ float g_xs[T_TOK];
__device__ __align__(16) int8_t g_sg8h[(size_t)IDIM * HDIM];
__device__ __align__(16) int8_t g_sg8l[(size_t)IDIM * HDIM];
__device__ __align__(16) int8_t g_su8h[(size_t)IDIM * HDIM];
__device__ __align__(16) int8_t g_su8l[(size_t)IDIM * HDIM];
__device__ __align__(16) int8_t g_sd8h[(size_t)HDIM * IDIM];
__device__ __align__(16) int8_t g_sd8l[(size_t)HDIM * IDIM];
__device__ __align__(16) int8_t g_eg8h[(size_t)NEXP * IDIM * HDIM];
__device__ __align__(16) int8_t g_eg8l[(size_t)NEXP * IDIM * HDIM];
__device__ __align__(16) int8_t g_eu8h[(size_t)NEXP * IDIM * HDIM];
__device__ __align__(16) int8_t g_eu8l[(size_t)NEXP * IDIM * HDIM];
__device__ __align__(16) int8_t g_ed8h[(size_t)NEXP * HDIM * IDIM];
__device__ __align__(16) int8_t g_ed8l[(size_t)NEXP * HDIM * IDIM];
__device__ float g_sgs[IDIM];
__device__ float g_sus[IDIM];
__device__ float g_sds[HDIM];
__device__ float g_egs[NEXP * IDIM];
__device__ float g_eus[NEXP * IDIM];
__device__ float g_eds[NEXP * HDIM];

// intermediates
__device__ float g_gbuf[(size_t)SLOTS * IDIM];
__device__ float g_ubuf[(size_t)SLOTS * IDIM];
__device__ __align__(16) int8_t g_hs8h[(size_t)T_TOK * IDIM];
__device__ __align__(16) int8_t g_hs8l[(size_t)T_TOK * IDIM];
__device__ float g_hss[T_TOK];
__device__ __align__(16) int8_t g_he8h[(size_t)SLOTS * IDIM];
__device__ __align__(16) int8_t g_he8l[(size_t)SLOTS * IDIM];
__device__ float g_hes[SLOTS];
__device__ float g_eout[(size_t)SLOTS * HDIM];

// routing
__device__ int   g_tok_e[T_TOK * 2];
__device__ float g_tok_w[T_TOK * 2];
__device__ int   g_tok_slot[T_TOK * 2];
__device__ int   g_counts[NEXP];
__device__ int   g_offsets[NEXP];
__device__ int   g_cursor[NEXP];
__device__ int   g_list_tok[SLOTS];
__device__ float g_list_w[SLOTS];

// ======================= PTX helpers (sm_80-era, compute_103-safe) =======================
__device__ __forceinline__ u32 smem_u32(const void* p) {
    u32 a;
    asm("{ .reg .u64 t; cvta.to.shared.u64 t, %1; cvt.u32.u64 %0, t; }" : "=r"(a) : "l"(p));
    return a;
}
__device__ __forceinline__ void cpa16(u32 dst, const void* src) {
    asm volatile("cp.async.cg.shared.global [%0], [%1], 16;"
                 :: "r"(dst), "l"(src) : "memory");
}
__device__ __forceinline__ void cpa_commit() {
    asm volatile("cp.async.commit_group;" ::: "memory");
}
__device__ __forceinline__ void ldsm4(u32* r, u32 addr) {
    asm volatile("ldmatrix.sync.aligned.m8n8.x4.shared.b16 {%0,%1,%2,%3}, [%4];"
                 : "=r"(r[0]), "=r"(r[1]), "=r"(r[2]), "=r"(r[3]) : "r"(addr));
}
__device__ __forceinline__ void mma_bf16(float* c, const u32* a, u32 b0, u32 b1) {
    asm volatile("mma.sync.aligned.m16n8k16.row.col.f32.bf16.bf16.f32 "
                 "{%0,%1,%2,%3}, {%4,%5,%6,%7}, {%8,%9}, {%0,%1,%2,%3};"
                 : "+f"(c[0]), "+f"(c[1]), "+f"(c[2]), "+f"(c[3])
                 : "r"(a[0]), "r"(a[1]), "r"(a[2]), "r"(a[3]), "r"(b0), "r"(b1));
}
__device__ __forceinline__ void mma_s8(int* c, const u32* a, u32 b0, u32 b1) {
    asm volatile("mma.sync.aligned.m16n8k32.row.col.s32.s8.s8.s32 "
                 "{%0,%1,%2,%3}, {%4,%5,%6,%7}, {%8,%9}, {%0,%1,%2,%3};"
                 : "+r"(c[0]), "+r"(c[1]), "+r"(c[2]), "+r"(c[3])
                 : "r"(a[0]), "r"(a[1]), "r"(a[2]), "r"(a[3]), "r"(b0), "r"(b1));
}

// ======================= small kernels =======================
__global__ void k_init() {
    int i = threadIdx.x;
    if (i < NEXP) { g_counts[i] = 0; g_cursor[i] = 0; }
}

// fp32 -> bf16 hi/lo split (router activations)
__global__ void k_split(const float* __restrict__ S, bf16* __restrict__ H,
                        bf16* __restrict__ L, int n4) {
    int i = blockIdx.x * blockDim.x + threadIdx.x;
    if (i >= n4) return;
    float4 v = ((const float4*)S)[i];
    union { bf16 b[4]; ushort4 u; } uh, ul;
    float vv[4] = { v.x, v.y, v.z, v.w };
#pragma unroll
    for (int j = 0; j < 4; j++) {
        bf16 h = __float2bfloat16(vv[j]);
        uh.b[j] = h;
        ul.b[j] = __float2bfloat16(vv[j] - __bfloat162float(h));
    }
    ((ushort4*)H)[i] = uh.u;
    ((ushort4*)L)[i] = ul.u;
}

// transpose + bf16 split (router weights)
__global__ void k_tsplit(const float* __restrict__ W, bf16* __restrict__ Th,
                         bf16* __restrict__ Tl, int K, int N) {
    size_t eo = (size_t)blockIdx.z * K * N;
    W += eo; Th += eo; Tl += eo;
    __shared__ float t[32][33];
    int k0 = blockIdx.y * 32, n0 = blockIdx.x * 32;
    int tx = threadIdx.x, ty = threadIdx.y;
#pragma unroll
    for (int q = 0; q < 4; q++)
        t[ty + 8 * q][tx] = W[(size_t)(k0 + ty + 8 * q) * N + n0 + tx];
    __syncthreads();
#pragma unroll
    for (int q = 0; q < 4; q++) {
        int n = ty + 8 * q;
        float v = t[tx][n];
        bf16 h = __float2bfloat16(v);
        bf16 l = __float2bfloat16(v - __bfloat162float(h));
        size_t o = (size_t)(n0 + n) * K + k0 + tx;
        Th[o] = h; Tl[o] = l;
    }
}

// per-token-row int8 2-limb quantization of x (K=HDIM=1024)
__global__ void k_aquant(const float* __restrict__ X, int8_t* __restrict__ Qh,
                         int8_t* __restrict__ Ql, float* __restrict__ S) {
    int row = blockIdx.x, tid = threadIdx.x;
    const float* xr = X + (size_t)row * HDIM;
    float4 v = ((const float4*)xr)[tid];
    float vv[4] = { v.x, v.y, v.z, v.w };
    float m = fmaxf(fmaxf(fabsf(vv[0]), fabsf(vv[1])), fmaxf(fabsf(vv[2]), fabsf(vv[3])));
    __shared__ float red[256];
    red[tid] = m; __syncthreads();
    for (int s = 128; s; s >>= 1) { if (tid < s) red[tid] = fmaxf(red[tid], red[tid + s]); __syncthreads(); }
    float mx = red[0];
    float sc = (mx > 0.f) ? mx / 16256.f : 1.f;
    if (tid == 0) S[row] = sc;
    float inv = 1.f / sc;
    char4 ch, cl;
    char* chp = (char*)&ch; char* clp = (char*)&cl;
#pragma unroll
    for (int j = 0; j < 4; j++) {
        float q = vv[j] * inv;
        float h = rintf(q * (1.f / 128.f));
        float l = rintf(q - h * 128.f);
        chp[j] = (char)(int)h; clp[j] = (char)(int)l;
    }
    ((char4*)(Qh + (size_t)row * HDIM))[tid] = ch;
    ((char4*)(Ql + (size_t)row * HDIM))[tid] = cl;
}

// per-output-column absmax of W [K,N] -> scale[n]
__global__ void k_wmax(const float* __restrict__ W, float* __restrict__ S, int K, int N) {
    size_t eo = (size_t)blockIdx.z * K * N;
    W += eo; S += (size_t)blockIdx.z * N;
    int tx = threadIdx.x, ty = threadIdx.y;
    int n = blockIdx.x * 32 + tx;
    float m = 0.f;
    for (int k = ty; k < K; k += 8) m = fmaxf(m, fabsf(W[(size_t)k * N + n]));
    __shared__ float red[8][33];
    red[ty][tx] = m; __syncthreads();
    if (ty == 0) {
#pragma unroll
        for (int j = 1; j < 8; j++) m = fmaxf(m, red[j][tx]);
        S[n] = (m > 0.f) ? m / 16256.f : 1.f;
    }
}

// transpose + int8 2-limb quantize: W [K,N] -> Th/Tl [N,K]
__global__ void k_tq(const float* __restrict__ W, int8_t* __restrict__ Th,
                     int8_t* __restrict__ Tl, const float* __restrict__ S, int K, int N) {
    size_t eo = (size_t)blockIdx.z * K * N;
    W += eo; Th += eo; Tl += eo; S += (size_t)blockIdx.z * N;
    __shared__ float t[32][33];
    int k0 = blockIdx.y * 32, n0 = blockIdx.x * 32;
    int tx = threadIdx.x, ty = threadIdx.y;
#pragma unroll
    for (int q = 0; q < 4; q++)
        t[ty + 8 * q][tx] = W[(size_t)(k0 + ty + 8 * q) * N + n0 + tx];
    __syncthreads();
#pragma unroll
    for (int q = 0; q < 4; q++) {
        int n = ty + 8 * q;
        float s = S[n0 + n];
        float qv = t[tx][n] / s;
        float h = rintf(qv * (1.f / 128.f));
        float l = rintf(qv - h * 128.f);
        size_t o = (size_t)(n0 + n) * K + k0 + tx;
        Th[o] = (int8_t)(int)h; Tl[o] = (int8_t)(int)l;
    }
}

// h = w * silu(g) * u, per-row int8 2-limb quantize (K=IDIM=2048)
__global__ void k_hquant(const float* __restrict__ G, const float* __restrict__ U,
                         int8_t* __restrict__ Qh, int8_t* __restrict__ Ql,
                         float* __restrict__ S, const float* __restrict__ wrow) {
    int row = blockIdx.x, tid = threadIdx.x;
    float w = wrow ? wrow[row] : 1.f;
    const float* g = G + (size_t)row * IDIM;
    const float* u = U + (size_t)row * IDIM;
    float vals[8]; float m = 0.f;
#pragma unroll
    for (int q = 0; q < 2; q++) {
        float4 gv = ((const float4*)g)[tid + q * 256];
        float4 uv = ((const float4*)u)[tid + q * 256];
        float gg[4] = { gv.x, gv.y, gv.z, gv.w };
        float uu[4] = { uv.x, uv.y, uv.z, uv.w };
#pragma unroll
        for (int j = 0; j < 4; j++) {
            float x = gg[j];
            float sig = 1.f / (1.f + __expf(-x));
            float v = w * (x * sig) * uu[j];
            vals[q * 4 + j] = v;
            m = fmaxf(m, fabsf(v));
        }
    }
    __shared__ float red[256];
    red[tid] = m; __syncthreads();
    for (int s = 128; s; s >>= 1) { if (tid < s) red[tid] = fmaxf(red[tid], red[tid + s]); __syncthreads(); }
    float mx = red[0];
    float sc = (mx > 0.f) ? mx / 16256.f : 1.f;
    if (tid == 0) S[row] = sc;
    float inv = 1.f / sc;
#pragma unroll
    for (int q = 0; q < 2; q++) {
        char4 ch, cl;
        char* chp = (char*)&ch; char* clp = (char*)&cl;
#pragma unroll
        for (int j = 0; j < 4; j++) {
            float qv = vals[q * 4 + j] * inv;
            float h = rintf(qv * (1.f / 128.f));
            float l = rintf(qv - h * 128.f);
            chp[j] = (char)(int)h; clp[j] = (char)(int)l;
        }
        ((char4*)(Qh + (size_t)row * IDIM))[tid + q * 256] = ch;
        ((char4*)(Ql + (size_t)row * IDIM))[tid + q * 256] = cl;
    }
}

// gate: logits, softmax, top-2, histogram (one warp / token)
__global__ void k_gate(const float* __restrict__ gw) {
    int t = (blockIdx.x * blockDim.x + threadIdx.x) >> 5;
    int lane = threadIdx.x & 31;
    if (t >= T_TOK) return;
    const float* xr = g_xr + (size_t)t * HDIM;
    float acc[8] = {0.f,0.f,0.f,0.f,0.f,0.f,0.f,0.f};
    for (int h = lane; h < HDIM; h += 32) {
        float xv = xr[h];
        float4 w0 = *(const float4*)(gw + (size_t)h * 8);
        float4 w1 = *(const float4*)(gw + (size_t)h * 8 + 4);
        acc[0] += xv * w0.x; acc[1] += xv * w0.y; acc[2] += xv * w0.z; acc[3] += xv * w0.w;
        acc[4] += xv * w1.x; acc[5] += xv * w1.y; acc[6] += xv * w1.z; acc[7] += xv * w1.w;
    }
#pragma unroll
    for (int o = 16; o; o >>= 1)
#pragma unroll
        for (int e = 0; e < 8; e++) acc[e] += __shfl_down_sync(0xffffffffu, acc[e], o);
    if (lane == 0) {
        float mx = acc[0];
#pragma unroll
        for (int e = 1; e < 8; e++) mx = fmaxf(mx, acc[e]);
        float p[8]; float Z = 0.f;
#pragma unroll
        for (int e = 0; e < 8; e++) { p[e] = __expf(acc[e] - mx); Z += p[e]; }
        float rZ = 1.f / Z;
#pragma unroll
        for (int e = 0; e < 8; e++) p[e] *= rZ;
        int i0 = 0; float p0 = p[0];
#pragma unroll
        for (int e = 1; e < 8; e++) if (p[e] > p0) { p0 = p[e]; i0 = e; }
        int i1 = -1; float p1 = -1.f;
#pragma unroll
        for (int e = 0; e < 8; e++) if (e != i0 && p[e] > p1) { p1 = p[e]; i1 = e; }
        float s = 1.f / (p0 + p1 + 1e-5f);
        g_tok_e[2*t] = i0;     g_tok_w[2*t] = p0 * s;
        g_tok_e[2*t+1] = i1;   g_tok_w[2*t+1] = p1 * s;
        atomicAdd(&g_counts[i0], 1); atomicAdd(&g_counts[i1], 1);
    }
}

__global__ void k_offsets() {
    if (threadIdx.x == 0) {
        int s = 0;
        for (int e = 0; e < NEXP; e++) { g_offsets[e] = s; s += g_counts[e]; g_cursor[e] = 0; }
    }
}

__global__ void k_place() {
    int t = blockIdx.x * blockDim.x + threadIdx.x;
    if (t >= T_TOK) return;
#pragma unroll
    for (int k = 0; k < 2; k++) {
        int e = g_tok_e[2*t + k];
        int pos = g_offsets[e] + atomicAdd(&g_cursor[e], 1);
        g_list_tok[pos] = t;
        g_list_w[pos] = g_tok_w[2*t + k];
        g_tok_slot[2*t + k] = pos;
    }
}

__global__ void k_combine(float* __restrict__ out) {
    int gid = blockIdx.x * blockDim.x + threadIdx.x;
    int t = gid / (HDIM / 4);
    int c = (gid % (HDIM / 4)) * 4;
    if (t >= T_TOK) return;
    int s0 = g_tok_slot[2*t], s1 = g_tok_slot[2*t+1];
    float4 o = *(const float4*)(out + (size_t)t * HDIM + c);
    float4 a = *(const float4*)(g_eout + (size_t)s0 * HDIM + c);
    float4 b = *(const float4*)(g_eout + (size_t)s1 * HDIM + c);
    o.x += a.x + b.x; o.y += a.y + b.y; o.z += a.z + b.z; o.w += a.w + b.w;
    *(float4*)(out + (size_t)t * HDIM + c) = o;
}

// ======================= bf16 HMMA GEMM (router only, 4-pass) =======================
#define CH_K   32
#define ROWB   80
#define MATB   (128 * ROWB)
#define STGB   (4 * MATB)
#define GEMM_SMEM (2 * STGB)

__global__ __launch_bounds__(256, 1) void k_gemm(
    const bf16* __restrict__ Ah, const bf16* __restrict__ Al,
    const bf16* __restrict__ Bh, const bf16* __restrict__ Bl,
    float* __restrict__ C, int Kdim, int Nld, int Mdense,
    const float* __restrict__ xadd, const float* __restrict__ bias)
{
    const int cnt = Mdense;
    const int m0 = blockIdx.y * 128;
    if (m0 >= cnt) return;
    const int n0 = blockIdx.x * 128;

    extern __shared__ char smem[];
    const u32 sb = smem_u32(smem);
    const int tid = threadIdx.x;

    const int lmat = tid >> 6;
    const int lrow0 = (tid & 63) * 2;
    const bf16* lbase = (lmat == 0) ? Ah : (lmat == 1) ? Al : (lmat == 2) ? Bh : Bl;
    const bool lisA = lmat < 2;

    const int nc = Kdim / CH_K;

#define LOAD_STAGE(c) do {                                                   \
        int _k0 = (c) * CH_K;                                                \
        u32 _db = sb + ((c) & 1) * STGB + lmat * MATB;                       \
        _Pragma("unroll")                                                    \
        for (int _rr = 0; _rr < 2; _rr++) {                                  \
            int _row = lrow0 + _rr;                                          \
            int _gr = lisA ? (m0 + _row) : (n0 + _row);                      \
            const bf16* _p = lbase + (size_t)_gr * Kdim + _k0;               \
            u32 _d = _db + _row * ROWB;                                      \
            cpa16(_d,      _p);                                              \
            cpa16(_d + 16, _p + 8);                                          \
            cpa16(_d + 32, _p + 16);                                         \
            cpa16(_d + 48, _p + 24);                                         \
        }                                                                    \
    } while (0)

    float acc[4][4][4];
#pragma unroll
    for (int i = 0; i < 4; i++)
#pragma unroll
        for (int j = 0; j < 4; j++)
#pragma unroll
            for (int q = 0; q < 4; q++) acc[i][j][q] = 0.f;

    const int wid = tid >> 5, lane = tid & 31;
    const int wm = wid >> 2, wn = wid & 3;
    const int a_r = wm * 64 + (lane & 15);
    const int a_kb = ((lane >> 4) & 1) * 16;
    const int b_g = lane >> 3, b_rl = lane & 7;
    const int b_nt = (b_g >> 1);
    const int b_kb = (b_g & 1) * 16;

    LOAD_STAGE(0);
    cpa_commit();

    for (int c = 0; c < nc; c++) {
        if (c + 1 < nc) LOAD_STAGE(c + 1);
        cpa_commit();
        asm volatile("cp.async.wait_group 1;" ::: "memory");
        __syncthreads();

        const u32 ab = sb + (c & 1) * STGB;
        const u32 bb = ab + 2 * MATB;

#pragma unroll
        for (int kk = 0; kk < 2; kk++) {
            const int kbyte = kk * 32;
            u32 ahf[4][4], alf[4][4], bhf[2][4], blf[2][4];
#pragma unroll
            for (int i = 0; i < 4; i++) {
                u32 ad = ab + (a_r + i * 16) * ROWB + kbyte + a_kb;
                ldsm4(ahf[i], ad);
                ldsm4(alf[i], ad + MATB);
            }
#pragma unroll
            for (int j = 0; j < 2; j++) {
                int nr = wn * 32 + (j * 2 + b_nt) * 8 + b_rl;
                u32 bd = bb + nr * ROWB + kbyte + b_kb;
                ldsm4(bhf[j], bd);
                ldsm4(blf[j], bd + MATB);
            }
#pragma unroll
            for (int i = 0; i < 4; i++)
#pragma unroll
                for (int nt = 0; nt < 4; nt++) {
                    float* cc = acc[i][nt];
                    u32 bh0 = bhf[nt >> 1][(nt & 1) * 2], bh1 = bhf[nt >> 1][(nt & 1) * 2 + 1];
                    u32 bl0 = blf[nt >> 1][(nt & 1) * 2], bl1 = blf[nt >> 1][(nt & 1) * 2 + 1];
                    mma_bf16(cc, ahf[i], bh0, bh1);
                    mma_bf16(cc, ahf[i], bl0, bl1);
                    mma_bf16(cc, alf[i], bh0, bh1);
                    mma_bf16(cc, alf[i], bl0, bl1);
                }
        }
        __syncthreads();
    }

#pragma unroll
    for (int i = 0; i < 4; i++) {
#pragma unroll
        for (int h = 0; h < 2; h++) {
            int lr = wm * 64 + i * 16 + (lane >> 2) + h * 8;
            int orow = m0 + lr;
            float* crow = C + (size_t)orow * Nld + n0 + wn * 32;
            const float* xr = xadd + (size_t)orow * HDIM + n0 + wn * 32;
            const float* bs = bias + n0 + wn * 32;
#pragma unroll
            for (int nt = 0; nt < 4; nt++) {
                int col = nt * 8 + (lane & 3) * 2;
                float v0 = acc[i][nt][h * 2]     + xr[col]     + bs[col];
                float v1 = acc[i][nt][h * 2 + 1] + xr[col + 1] + bs[col + 1];
                *(float2*)(crow + col) = make_float2(v0, v1);
            }
        }
    }
#undef LOAD_STAGE
}

// ======================= INT8 2-limb IMMA GEMM =======================
// C[M,N] = sa[m]*sw[n]*(16384*sum(ah*wh) + 128*sum(ah*wl + al*wh))
// A limbs [rows,K] s8, B limbs pre-transposed [N,K] s8.
// CTA 128x128, K-chunk 64, 3-stage cp.async ring, 8 warps (warp tile 64x32).
// mode: 0 dense, 1 gathered tokens (per expert), 2 slot rows (per expert)
#define ICH    64
#define IROWB  80
#define IMATB  (128 * IROWB)
#define ISTGB  (4 * IMATB)       // 40960
#define I8_SMEM (3 * ISTGB)      // 122880

__global__ __launch_bounds__(256, 1) void k_gemm_i8(
    const int8_t* __restrict__ Ah, const int8_t* __restrict__ Al,
    const int8_t* __restrict__ Bh, const int8_t* __restrict__ Bl,
    const float* __restrict__ sa, const float* __restrict__ sw,
    float* __restrict__ C, int Kdim, int Nld, int Mdense, int mode)
{
    int cnt, off;
    if (mode == 0) { cnt = Mdense; off = 0; }
    else {
        int e = blockIdx.z;
        cnt = g_counts[e]; off = g_offsets[e];
        size_t wo = (size_t)e * Nld * Kdim;
        Bh += wo; Bl += wo; sw += (size_t)e * Nld;
    }
    const int m0 = blockIdx.y * 128;
    if (m0 >= cnt) return;
    const int n0 = blockIdx.x * 128;

    extern __shared__ char smem[];
    __shared__ int s_arow[128];
    const u32 sb = smem_u32(smem);
    const int tid = threadIdx.x;

    if (tid < 128) {
        int gr;
        if (mode == 0) gr = m0 + tid;
        else {
            int mr = m0 + tid; if (mr > cnt - 1) mr = cnt - 1;
            gr = (mode == 1) ? g_list_tok[off + mr] : (off + mr);
        }
        s_arow[tid] = gr;
    }
    __syncthreads();

    const int lmat = tid >> 6;
    const int lrow0 = (tid & 63) * 2;
    const int8_t* lbase = (lmat == 0) ? Ah : (lmat == 1) ? Al : (lmat == 2) ? Bh : Bl;
    const bool lisA = lmat < 2;
    const int nc = Kdim / ICH;

#define ILOAD(c) do {                                                        \
        int _k0 = (c) * ICH;                                                 \
        u32 _db = sb + ((c) % 3) * ISTGB + lmat * IMATB;                     \
        _Pragma("unroll")                                                    \
        for (int _rr = 0; _rr < 2; _rr++) {                                  \
            int _row = lrow0 + _rr;                                          \
            int _gr = lisA ? s_arow[_row] : (n0 + _row);                     \
            const int8_t* _p = lbase + (size_t)_gr * Kdim + _k0;             \
            u32 _d = _db + _row * IROWB;                                     \
            cpa16(_d,      _p);                                              \
            cpa16(_d + 16, _p + 16);                                         \
            cpa16(_d + 32, _p + 32);                                         \
            cpa16(_d + 48, _p + 48);                                         \
        }                                                                    \
    } while (0)

    int acc0[4][4][4], acc1[4][4][4];
#pragma unroll
    for (int i = 0; i < 4; i++)
#pragma unroll
        for (int j = 0; j < 4; j++)
#pragma unroll
            for (int q = 0; q < 4; q++) { acc0[i][j][q] = 0; acc1[i][j][q] = 0; }

    const int wid = tid >> 5, lane = tid & 31;
    const int wm = wid >> 2, wn = wid & 3;     // 2x4 warps -> 64x32 warp tile
    const int fr = lane & 15;                  // fragment row
    const int fk = ((lane >> 4) & 1) * 16;     // k 16B-half select

    ILOAD(0); cpa_commit();
    ILOAD(1); cpa_commit();

    for (int c = 0; c < nc; c++) {
        if (c < nc - 1) asm volatile("cp.async.wait_group 1;" ::: "memory");
        else            asm volatile("cp.async.wait_group 0;" ::: "memory");
        __syncthreads();
        if (c + 2 < nc) { ILOAD(c + 2); cpa_commit(); }

        const u32 ab = sb + (c % 3) * ISTGB;
        const u32 bb = ab + 2 * IMATB;

#pragma unroll
        for (int kk = 0; kk < 2; kk++) {
            const int kb = kk * 32;
            u32 ahf[4][4], alf[4][4], bhf[2][4], blf[2][4];
#pragma unroll
            for (int i = 0; i < 4; i++) {
                u32 ad = ab + (wm * 64 + i * 16 + fr) * IROWB + kb + fk;
                ldsm4(ahf[i], ad);
                ldsm4(alf[i], ad + IMATB);
            }
#pragma unroll
            for (int j = 0; j < 2; j++) {
                u32 bd = bb + (wn * 32 + j * 16 + fr) * IROWB + kb + fk;
                ldsm4(bhf[j], bd);
                ldsm4(blf[j], bd + IMATB);
            }
#pragma unroll
            for (int i = 0; i < 4; i++)
#pragma unroll
                for (int nt = 0; nt < 4; nt++) {
                    int j = nt >> 1, t = nt & 1;
                    u32 b0h = bhf[j][t], b1h = bhf[j][t + 2];
                    u32 b0l = blf[j][t], b1l = blf[j][t + 2];
                    mma_s8(acc0[i][nt], ahf[i], b0h, b1h);
                    mma_s8(acc1[i][nt], ahf[i], b0l, b1l);
                    mma_s8(acc1[i][nt], alf[i], b0h, b1h);
                }
        }
        __syncthreads();
    }

#pragma unroll
    for (int i = 0; i < 4; i++) {
#pragma unroll
        for (int h = 0; h < 2; h++) {
            int lr = wm * 64 + i * 16 + (lane >> 2) + h * 8;
            if (m0 + lr < cnt) {
                int orow = (mode == 0 ? 0 : off) + m0 + lr;
                float sA = sa[s_arow[lr]];
                float* crow = C + (size_t)orow * Nld + n0 + wn * 32;
                const float* swp = sw + n0 + wn * 32;
#pragma unroll
                for (int nt = 0; nt < 4; nt++) {
                    int col = nt * 8 + (lane & 3) * 2;
                    float v0 = sA * swp[col] *
                        (16384.f * (float)acc0[i][nt][h*2]   + 128.f * (float)acc1[i][nt][h*2]);
                    float v1 = sA * swp[col + 1] *
                        (16384.f * (float)acc0[i][nt][h*2+1] + 128.f * (float)acc1[i][nt][h*2+1]);
                    *(float2*)(crow + col) = make_float2(v0, v1);
                }
            }
        }
    }
#undef ILOAD
}

// ======================= launch =======================
extern "C" void kernel_launch(void* const* d_in, const int* in_sizes, int n_in,
                              void* d_out, int out_size) {
    const float* x   = (const float*)d_in[0];
    const float* tcx = (const float*)d_in[1];
    const float* tpw = (const float*)d_in[2];
    const float* tpb = (const float*)d_in[3];
    const float* gw  = (const float*)d_in[4];
    const float* eg  = (const float*)d_in[5];
    const float* eu  = (const float*)d_in[6];
    const float* ed  = (const float*)d_in[7];
    const float* sg  = (const float*)d_in[8];
    const float* su  = (const float*)d_in[9];
    const float* sd  = (const float*)d_in[10];
    float* out = (float*)d_out;

    cudaFuncSetAttribute(k_gemm, cudaFuncAttributeMaxDynamicSharedMemorySize, GEMM_SMEM);
    cudaFuncSetAttribute(k_gemm_i8, cudaFuncAttributeMaxDynamicSharedMemorySize, I8_SMEM);

    bf16 *tch, *tcl, *tpwTh, *tpwTl;
    int8_t *x8h, *x8l, *sg8h, *sg8l, *su8h, *su8l, *sd8h, *sd8l;
    int8_t *eg8h, *eg8l, *eu8h, *eu8l, *ed8h, *ed8l;
    int8_t *hs8h, *hs8l, *he8h, *he8l;
    float *xs, *sgs, *sus, *sds, *egs, *eus, *eds, *hss, *hes;
    float *xr, *gbuf, *ubuf, *eout, *listw;
    cudaGetSymbolAddress((void**)&tch, g_tch);   cudaGetSymbolAddress((void**)&tcl, g_tcl);
    cudaGetSymbolAddress((void**)&tpwTh, g_tpwT_h); cudaGetSymbolAddress((void**)&tpwTl, g_tpwT_l);
    cudaGetSymbolAddress((void**)&x8h, g_x8h);   cudaGetSymbolAddress((void**)&x8l, g_x8l);
    cudaGetSymbolAddress((void**)&sg8h, g_sg8h); cudaGetSymbolAddress((void**)&sg8l, g_sg8l);
    cudaGetSymbolAddress((void**)&su8h, g_su8h); cudaGetSymbolAddress((void**)&su8l, g_su8l);
    cudaGetSymbolAddress((void**)&sd8h, g_sd8h); cudaGetSymbolAddress((void**)&sd8l, g_sd8l);
    cudaGetSymbolAddress((void**)&eg8h, g_eg8h); cudaGetSymbolAddress((void**)&eg8l, g_eg8l);
    cudaGetSymbolAddress((void**)&eu8h, g_eu8h); cudaGetSymbolAddress((void**)&eu8l, g_eu8l);
    cudaGetSymbolAddress((void**)&ed8h, g_ed8h); cudaGetSymbolAddress((void**)&ed8l, g_ed8l);
    cudaGetSymbolAddress((void**)&hs8h, g_hs8h); cudaGetSymbolAddress((void**)&hs8l, g_hs8l);
    cudaGetSymbolAddress((void**)&he8h, g_he8h); cudaGetSymbolAddress((void**)&he8l, g_he8l);
    cudaGetSymbolAddress((void**)&xs, g_xs);
    cudaGetSymbolAddress((void**)&sgs, g_sgs);   cudaGetSymbolAddress((void**)&sus, g_sus);
    cudaGetSymbolAddress((void**)&sds, g_sds);
    cudaGetSymbolAddress((void**)&egs, g_egs);   cudaGetSymbolAddress((void**)&eus, g_eus);
    cudaGetSymbolAddress((void**)&eds, g_eds);
    cudaGetSymbolAddress((void**)&hss, g_hss);   cudaGetSymbolAddress((void**)&hes, g_hes);
    cudaGetSymbolAddress((void**)&xr, g_xr);
    cudaGetSymbolAddress((void**)&gbuf, g_gbuf); cudaGetSymbolAddress((void**)&ubuf, g_ubuf);
    cudaGetSymbolAddress((void**)&eout, g_eout);
    cudaGetSymbolAddress((void**)&listw, g_list_w);

    dim3 wb(32, 8);

    // 0
    k_init<<<1, 32>>>();
    // 1: quantize x (int8 2-limb, per token row)
    k_aquant<<<T_TOK, 256>>>(x, x8h, x8l, xs);
    // 2-3: shared gate weights
    k_wmax<<<dim3(IDIM/32, 1, 1), wb>>>(sg, sgs, HDIM, IDIM);
    k_tq<<<dim3(IDIM/32, HDIM/32, 1), wb>>>(sg, sg8h, sg8l, sgs, HDIM, IDIM);
    // 4
    k_wmax<<<dim3(IDIM/32, 1, 1), wb>>>(su, sus, HDIM, IDIM);
    // 5: shared gate GEMM  <-- ncu capture target
    k_gemm_i8<<<dim3(IDIM/128, T_TOK/128, 1), 256, I8_SMEM>>>(
        x8h, x8l, sg8h, sg8l, xs, sgs, gbuf, HDIM, IDIM, T_TOK, 0);
    // 6-7
    k_tq<<<dim3(IDIM/32, HDIM/32, 1), wb>>>(su, su8h, su8l, sus, HDIM, IDIM);
    k_gemm_i8<<<dim3(IDIM/128, T_TOK/128, 1), 256, I8_SMEM>>>(
        x8h, x8l, su8h, su8l, xs, sus, ubuf, HDIM, IDIM, T_TOK, 0);
    // 8-9: shared down weights
    k_wmax<<<dim3(HDIM/32, 1, 1), wb>>>(sd, sds, IDIM, HDIM);
    k_tq<<<dim3(HDIM/32, IDIM/32, 1), wb>>>(sd, sd8h, sd8l, sds, IDIM, HDIM);
    // 10-12: router (bf16 4-pass, high precision)
    {
        int n4 = T_TOK * HDIM / 4;
        k_split<<<n4 / 256, 256>>>(tcx, tch, tcl, n4);
    }
    k_tsplit<<<dim3(HDIM/32, HDIM/32, 1), wb>>>(tpw, tpwTh, tpwTl, HDIM, HDIM);
    k_gemm<<<dim3(HDIM/128, T_TOK/128, 1), 256, GEMM_SMEM>>>(
        tch, tcl, tpwTh, tpwTl, xr, HDIM, HDIM, T_TOK, x, tpb);
    // 13-15: routing
    k_gate<<<T_TOK / 8, 256>>>(gw);
    k_offsets<<<1, 32>>>();
    k_place<<<T_TOK / 256, 256>>>();
    // 16: shared h quantize
    k_hquant<<<T_TOK, 256>>>(gbuf, ubuf, hs8h, hs8l, hss, nullptr);
    // 17: shared down -> out
    k_gemm_i8<<<dim3(HDIM/128, T_TOK/128, 1), 256, I8_SMEM>>>(
        hs8h, hs8l, sd8h, sd8l, hss, sds, out, IDIM, HDIM, T_TOK, 0);
    // 18-23: expert weights
    k_wmax<<<dim3(IDIM/32, 1, NEXP), wb>>>(eg, egs, HDIM, IDIM);
    k_tq<<<dim3(IDIM/32, HDIM/32, NEXP), wb>>>(eg, eg8h, eg8l, egs, HDIM, IDIM);
    k_wmax<<<dim3(IDIM/32, 1, NEXP), wb>>>(eu, eus, HDIM, IDIM);
    k_tq<<<dim3(IDIM/32, HDIM/32, NEXP), wb>>>(eu, eu8h, eu8l, eus, HDIM, IDIM);
    k_wmax<<<dim3(HDIM/32, 1, NEXP), wb>>>(ed, eds, IDIM, HDIM);
    k_tq<<<dim3(HDIM/32, IDIM/32, NEXP), wb>>>(ed, ed8h, ed8l, eds, IDIM, HDIM);
    // 24-25: expert gate/up (gathered)
    k_gemm_i8<<<dim3(IDIM/128, SLOTS/128, NEXP), 256, I8_SMEM>>>(
        x8h, x8l, eg8h, eg8l, xs, egs, gbuf, HDIM, IDIM, 0, 1);
    k_gemm_i8<<<dim3(IDIM/128, SLOTS/128, NEXP), 256, I8_SMEM>>>(
        x8h, x8l, eu8h, eu8l, xs, eus, ubuf, HDIM, IDIM, 0, 1);
    // 26: expert h quantize (with combine weight folded)
    k_hquant<<<SLOTS, 256>>>(gbuf, ubuf, he8h, he8l, hes, listw);
    // 27: expert down -> per-slot scratch
    k_gemm_i8<<<dim3(HDIM/128, SLOTS/128, NEXP), 256, I8_SMEM>>>(
        he8h, he8l, ed8h, ed8l, hes, eds, eout, IDIM, HDIM, 0, 2);
    // 28: combine
    k_combine<<<(T_TOK * (HDIM / 4)) / 256, 256>>>(out);
}

// round 7
// speedup vs baseline: 2.3512x; 2.3512x over previous
#include <cuda_runtime.h>
#include <cuda_bf16.h>
#include <stdint.h>
#include <math.h>

typedef __nv_bfloat16 bf16;
typedef unsigned long long u64;
typedef unsigned int u32;

#define T_TOK 4096
#define HDIM  1024
#define IDIM  2048
#define NEXP  8
#define SLOTS (2 * T_TOK)

// ======================= scratch (device globals) =======================
__device__ __align__(16) bf16 g_xh[(size_t)T_TOK * HDIM];
__device__ __align__(16) bf16 g_xl[(size_t)T_TOK * HDIM];
__device__ __align__(16) bf16 g_tch[(size_t)T_TOK * HDIM];
__device__ __align__(16) bf16 g_tcl[(size_t)T_TOK * HDIM];
__device__ __align__(16) bf16 g_tpwT_h[(size_t)HDIM * HDIM];
__device__ __align__(16) bf16 g_tpwT_l[(size_t)HDIM * HDIM];
__device__ __align__(16) bf16 g_sgT_h[(size_t)IDIM * HDIM];
__device__ __align__(16) bf16 g_sgT_l[(size_t)IDIM * HDIM];
__device__ __align__(16) bf16 g_suT_h[(size_t)IDIM * HDIM];
__device__ __align__(16) bf16 g_suT_l[(size_t)IDIM * HDIM];
__device__ __align__(16) bf16 g_sdT_h[(size_t)HDIM * IDIM];
__device__ __align__(16) bf16 g_sdT_l[(size_t)HDIM * IDIM];
__device__ __align__(16) bf16 g_egT_h[(size_t)NEXP * IDIM * HDIM];
__device__ __align__(16) bf16 g_egT_l[(size_t)NEXP * IDIM * HDIM];
__device__ __align__(16) bf16 g_euT_h[(size_t)NEXP * IDIM * HDIM];
__device__ __align__(16) bf16 g_euT_l[(size_t)NEXP * IDIM * HDIM];
__device__ __align__(16) bf16 g_edT_h[(size_t)NEXP * HDIM * IDIM];
__device__ __align__(16) bf16 g_edT_l[(size_t)NEXP * HDIM * IDIM];

__device__ float g_xr[(size_t)T_TOK * HDIM];
__device__ float g_gbuf[(size_t)SLOTS * IDIM];
__device__ float g_ubuf[(size_t)SLOTS * IDIM];
__device__ __align__(16) bf16 g_hsh[(size_t)T_TOK * IDIM];
__device__ __align__(16) bf16 g_hsl[(size_t)T_TOK * IDIM];
__device__ __align__(16) bf16 g_hh[(size_t)SLOTS * IDIM];
__device__ __align__(16) bf16 g_hl[(size_t)SLOTS * IDIM];
__device__ float g_eout[(size_t)SLOTS * HDIM];

__device__ int   g_tok_e[T_TOK * 2];
__device__ float g_tok_w[T_TOK * 2];
__device__ int   g_tok_slot[T_TOK * 2];
__device__ int   g_counts[NEXP];
__device__ int   g_offsets[NEXP];
__device__ int   g_cursor[NEXP];
__device__ int   g_list_tok[SLOTS];
__device__ float g_list_w[SLOTS];

// ======================= PTX helpers (sm_80-era, compute_103-safe) =======================
__device__ __forceinline__ u32 smem_u32(const void* p) {
    u32 a;
    asm("{ .reg .u64 t; cvta.to.shared.u64 t, %1; cvt.u32.u64 %0, t; }" : "=r"(a) : "l"(p));
    return a;
}
__device__ __forceinline__ void cpa16(u32 dst, const void* src) {
    asm volatile("cp.async.cg.shared.global [%0], [%1], 16;"
                 :: "r"(dst), "l"(src) : "memory");
}
__device__ __forceinline__ void cpa_commit() {
    asm volatile("cp.async.commit_group;" ::: "memory");
}
__device__ __forceinline__ void ldsm4(u32* r, u32 addr) {
    asm volatile("ldmatrix.sync.aligned.m8n8.x4.shared.b16 {%0,%1,%2,%3}, [%4];"
                 : "=r"(r[0]), "=r"(r[1]), "=r"(r[2]), "=r"(r[3]) : "r"(addr));
}
__device__ __forceinline__ void mma_bf16(float* c, const u32* a, u32 b0, u32 b1) {
    asm volatile("mma.sync.aligned.m16n8k16.row.col.f32.bf16.bf16.f32 "
                 "{%0,%1,%2,%3}, {%4,%5,%6,%7}, {%8,%9}, {%0,%1,%2,%3};"
                 : "+f"(c[0]), "+f"(c[1]), "+f"(c[2]), "+f"(c[3])
                 : "r"(a[0]), "r"(a[1]), "r"(a[2]), "r"(a[3]), "r"(b0), "r"(b1));
}

// ======================= small kernels =======================
__global__ void k_init() {
    int i = threadIdx.x;
    if (i < NEXP) { g_counts[i] = 0; g_cursor[i] = 0; }
}

__global__ void k_split(const float* __restrict__ S, bf16* __restrict__ H,
                        bf16* __restrict__ L, int n4) {
    int i = blockIdx.x * blockDim.x + threadIdx.x;
    if (i >= n4) return;
    float4 v = ((const float4*)S)[i];
    union { bf16 b[4]; ushort4 u; } uh, ul;
    float vv[4] = { v.x, v.y, v.z, v.w };
#pragma unroll
    for (int j = 0; j < 4; j++) {
        bf16 h = __float2bfloat16(vv[j]);
        uh.b[j] = h;
        ul.b[j] = __float2bfloat16(vv[j] - __bfloat162float(h));
    }
    ((ushort4*)H)[i] = uh.u;
    ((ushort4*)L)[i] = ul.u;
}

// transpose + split: W [K,N] fp32 -> Th/Tl [N,K] bf16 (z = expert)
__global__ void k_tsplit(const float* __restrict__ W, bf16* __restrict__ Th,
                         bf16* __restrict__ Tl, int K, int N) {
    size_t eo = (size_t)blockIdx.z * K * N;
    W += eo; Th += eo; Tl += eo;
    __shared__ float t[32][33];
    int k0 = blockIdx.y * 32, n0 = blockIdx.x * 32;
    int tx = threadIdx.x, ty = threadIdx.y;
#pragma unroll
    for (int q = 0; q < 4; q++)
        t[ty + 8 * q][tx] = W[(size_t)(k0 + ty + 8 * q) * N + n0 + tx];
    __syncthreads();
#pragma unroll
    for (int q = 0; q < 4; q++) {
        int n = ty + 8 * q;
        float v = t[tx][n];
        bf16 h = __float2bfloat16(v);
        bf16 l = __float2bfloat16(v - __bfloat162float(h));
        size_t o = (size_t)(n0 + n) * K + k0 + tx;
        Th[o] = h; Tl[o] = l;
    }
}

__global__ void k_gate(const float* __restrict__ gw) {
    int t = (blockIdx.x * blockDim.x + threadIdx.x) >> 5;
    int lane = threadIdx.x & 31;
    if (t >= T_TOK) return;
    const float* xr = g_xr + (size_t)t * HDIM;
    float acc[8] = {0.f,0.f,0.f,0.f,0.f,0.f,0.f,0.f};
    for (int h = lane; h < HDIM; h += 32) {
        float xv = xr[h];
        float4 w0 = *(const float4*)(gw + (size_t)h * 8);
        float4 w1 = *(const float4*)(gw + (size_t)h * 8 + 4);
        acc[0] += xv * w0.x; acc[1] += xv * w0.y; acc[2] += xv * w0.z; acc[3] += xv * w0.w;
        acc[4] += xv * w1.x; acc[5] += xv * w1.y; acc[6] += xv * w1.z; acc[7] += xv * w1.w;
    }
#pragma unroll
    for (int o = 16; o; o >>= 1)
#pragma unroll
        for (int e = 0; e < 8; e++) acc[e] += __shfl_down_sync(0xffffffffu, acc[e], o);
    if (lane == 0) {
        float mx = acc[0];
#pragma unroll
        for (int e = 1; e < 8; e++) mx = fmaxf(mx, acc[e]);
        float p[8]; float Z = 0.f;
#pragma unroll
        for (int e = 0; e < 8; e++) { p[e] = __expf(acc[e] - mx); Z += p[e]; }
        float rZ = 1.f / Z;
#pragma unroll
        for (int e = 0; e < 8; e++) p[e] *= rZ;
        int i0 = 0; float p0 = p[0];
#pragma unroll
        for (int e = 1; e < 8; e++) if (p[e] > p0) { p0 = p[e]; i0 = e; }
        int i1 = -1; float p1 = -1.f;
#pragma unroll
        for (int e = 0; e < 8; e++) if (e != i0 && p[e] > p1) { p1 = p[e]; i1 = e; }
        float s = 1.f / (p0 + p1 + 1e-5f);
        g_tok_e[2*t] = i0;     g_tok_w[2*t] = p0 * s;
        g_tok_e[2*t+1] = i1;   g_tok_w[2*t+1] = p1 * s;
        atomicAdd(&g_counts[i0], 1); atomicAdd(&g_counts[i1], 1);
    }
}

__global__ void k_offsets() {
    if (threadIdx.x == 0) {
        int s = 0;
        for (int e = 0; e < NEXP; e++) { g_offsets[e] = s; s += g_counts[e]; g_cursor[e] = 0; }
    }
}

__global__ void k_place() {
    int t = blockIdx.x * blockDim.x + threadIdx.x;
    if (t >= T_TOK) return;
#pragma unroll
    for (int k = 0; k < 2; k++) {
        int e = g_tok_e[2*t + k];
        int pos = g_offsets[e] + atomicAdd(&g_cursor[e], 1);
        g_list_tok[pos] = t;
        g_list_w[pos] = g_tok_w[2*t + k];
        g_tok_slot[2*t + k] = pos;
    }
}

__global__ void k_silu(const float* __restrict__ G, const float* __restrict__ U,
                       bf16* __restrict__ Hh, bf16* __restrict__ Hl,
                       const float* __restrict__ wrow, int n4) {
    int i = blockIdx.x * blockDim.x + threadIdx.x;
    if (i >= n4) return;
    int row = i / (IDIM / 4);
    float w = wrow ? wrow[row] : 1.0f;
    float4 g = ((const float4*)G)[i];
    float4 u = ((const float4*)U)[i];
    float gg[4] = { g.x, g.y, g.z, g.w };
    float uu[4] = { u.x, u.y, u.z, u.w };
    union { bf16 b[4]; ushort4 us; } uh, ul;
#pragma unroll
    for (int j = 0; j < 4; j++) {
        float gv = gg[j];
        float sig = 1.f / (1.f + __expf(-gv));
        float h = w * (gv * sig) * uu[j];
        bf16 hb = __float2bfloat16(h);
        uh.b[j] = hb;
        ul.b[j] = __float2bfloat16(h - __bfloat162float(hb));
    }
    ((ushort4*)Hh)[i] = uh.us;
    ((ushort4*)Hl)[i] = ul.us;
}

__global__ void k_combine(float* __restrict__ out) {
    int gid = blockIdx.x * blockDim.x + threadIdx.x;
    int t = gid / (HDIM / 4);
    int c = (gid % (HDIM / 4)) * 4;
    if (t >= T_TOK) return;
    int s0 = g_tok_slot[2*t], s1 = g_tok_slot[2*t+1];
    float4 o = *(const float4*)(out + (size_t)t * HDIM + c);
    float4 a = *(const float4*)(g_eout + (size_t)s0 * HDIM + c);
    float4 b = *(const float4*)(g_eout + (size_t)s1 * HDIM + c);
    o.x += a.x + b.x; o.y += a.y + b.y; o.z += a.z + b.z; o.w += a.w + b.w;
    *(float4*)(out + (size_t)t * HDIM + c) = o;
}

// ======================= bf16 HMMA GEMM (3-stage, batched LDSM) =======================
// C[M,N] = A @ B^T with bf16 hi/lo error compensation (3 or 4 passes).
// CTA 128x128, K-chunk 32, 3-stage cp.async ring, 8 warps (warp tile 64x32),
// one __syncthreads per chunk, all chunk LDSM batched before MMA.
// mode: 0 dense rows, 1 gathered (token list per expert), 2 slot rows (per expert)
// epi:  0 plain fp32 store, 1 router (+x +bias)
#define CH_K   32
#define ROWB   80
#define MATB   (128 * ROWB)          // 10240
#define STGB   (4 * MATB)            // 40960
#define NSTG   3
#define GEMM_SMEM (NSTG * STGB)      // 122880

__global__ __launch_bounds__(256, 1) void k_gemm(
    const bf16* __restrict__ Ah, const bf16* __restrict__ Al,
    const bf16* __restrict__ Bh, const bf16* __restrict__ Bl,
    float* __restrict__ C, int Kdim, int Nld,
    int Mdense, int mode, int epi, int npass,
    const float* __restrict__ xadd, const float* __restrict__ bias)
{
    int cnt, off;
    if (mode == 0) { cnt = Mdense; off = 0; }
    else {
        int e = blockIdx.z;
        cnt = g_counts[e]; off = g_offsets[e];
        size_t wo = (size_t)e * Nld * Kdim;
        Bh += wo; Bl += wo;
    }
    const int m0 = blockIdx.y * 128;
    if (m0 >= cnt) return;
    const int n0 = blockIdx.x * 128;

    extern __shared__ char smem[];
    __shared__ int s_arow[128];
    const u32 sb = smem_u32(smem);
    const int tid = threadIdx.x;

    if (tid < 128) {
        int gr;
        if (mode == 0) gr = m0 + tid;
        else {
            int mr = m0 + tid; if (mr > cnt - 1) mr = cnt - 1;
            gr = (mode == 1) ? g_list_tok[off + mr] : (off + mr);
        }
        s_arow[tid] = gr;
    }
    __syncthreads();

    // loader: 4 matrices x 64 threads; each thread: 2 rows x 4 x 16B
    const int lmat = tid >> 6;
    const int lrow0 = (tid & 63) * 2;
    const bf16* lbase = (lmat == 0) ? Ah : (lmat == 1) ? Al : (lmat == 2) ? Bh : Bl;
    const bool lisA = lmat < 2;
    const int nc = Kdim / CH_K;

#define LOAD_STAGE(c) do {                                                   \
        int _k0 = (c) * CH_K;                                                \
        u32 _db = sb + ((c) % NSTG) * STGB + lmat * MATB;                    \
        _Pragma("unroll")                                                    \
        for (int _rr = 0; _rr < 2; _rr++) {                                  \
            int _row = lrow0 + _rr;                                          \
            int _gr = lisA ? s_arow[_row] : (n0 + _row);                     \
            const bf16* _p = lbase + (size_t)_gr * Kdim + _k0;               \
            u32 _d = _db + _row * ROWB;                                      \
            cpa16(_d,      _p);                                              \
            cpa16(_d + 16, _p + 8);                                          \
            cpa16(_d + 32, _p + 16);                                         \
            cpa16(_d + 48, _p + 24);                                         \
        }                                                                    \
    } while (0)

    float acc[4][4][4];
#pragma unroll
    for (int i = 0; i < 4; i++)
#pragma unroll
        for (int j = 0; j < 4; j++)
#pragma unroll
            for (int q = 0; q < 4; q++) acc[i][j][q] = 0.f;

    const int wid = tid >> 5, lane = tid & 31;
    const int wm = wid >> 2, wn = wid & 3;     // 2x4 warps -> 64x32 warp tile
    const int fr = lane & 15;                  // fragment row
    const int fk = ((lane >> 4) & 1) * 16;     // k 16B-half select

    LOAD_STAGE(0); cpa_commit();
    LOAD_STAGE(1); cpa_commit();

    for (int c = 0; c < nc; c++) {
        if (c < nc - 1) asm volatile("cp.async.wait_group 1;" ::: "memory");
        else            asm volatile("cp.async.wait_group 0;" ::: "memory");
        __syncthreads();
        if (c + 2 < nc) LOAD_STAGE(c + 2);
        cpa_commit();

        const u32 ab = sb + (c % NSTG) * STGB;
        const u32 bb = ab + 2 * MATB;

        // ---- batch ALL chunk fragments (both k16 halves, both limbs) ----
        u32 ahf[2][4][4], alf[2][4][4], bhf[2][2][4], blf[2][2][4];
#pragma unroll
        for (int kk = 0; kk < 2; kk++) {
            const int kb = kk * 32;
#pragma unroll
            for (int i = 0; i < 4; i++) {
                u32 ad = ab + (wm * 64 + i * 16 + fr) * ROWB + kb + fk;
                ldsm4(ahf[kk][i], ad);
                ldsm4(alf[kk][i], ad + MATB);
            }
#pragma unroll
            for (int j = 0; j < 2; j++) {
                u32 bd = bb + (wn * 32 + j * 16 + fr) * ROWB + kb + fk;
                ldsm4(bhf[kk][j], bd);
                ldsm4(blf[kk][j], bd + MATB);
            }
        }
        // ---- all MMAs ----
#pragma unroll
        for (int kk = 0; kk < 2; kk++) {
#pragma unroll
            for (int i = 0; i < 4; i++)
#pragma unroll
                for (int nt = 0; nt < 4; nt++) {
                    int j = nt >> 1, t = nt & 1;
                    float* cc = acc[i][nt];
                    u32 b0h = bhf[kk][j][t], b1h = bhf[kk][j][t + 2];
                    u32 b0l = blf[kk][j][t], b1l = blf[kk][j][t + 2];
                    mma_bf16(cc, ahf[kk][i], b0h, b1h);
                    mma_bf16(cc, ahf[kk][i], b0l, b1l);
                    mma_bf16(cc, alf[kk][i], b0h, b1h);
                    if (npass == 4) mma_bf16(cc, alf[kk][i], b0l, b1l);
                }
        }
    }

    // epilogue: rows wm*64 + i*16 + lane/4 + {0,8}; cols wn*32 + nt*8 + (lane%4)*2 + {0,1}
#pragma unroll
    for (int i = 0; i < 4; i++) {
#pragma unroll
        for (int h = 0; h < 2; h++) {
            int lr = wm * 64 + i * 16 + (lane >> 2) + h * 8;
            if (m0 + lr < cnt) {
                int orow = (mode == 0 ? 0 : off) + m0 + lr;
                float* crow = C + (size_t)orow * Nld + n0 + wn * 32;
                const float* xr = (epi == 1) ? (xadd + (size_t)(m0 + lr) * HDIM + n0 + wn * 32) : nullptr;
                const float* bs = (epi == 1) ? (bias + n0 + wn * 32) : nullptr;
#pragma unroll
                for (int nt = 0; nt < 4; nt++) {
                    int col = nt * 8 + (lane & 3) * 2;
                    float v0 = acc[i][nt][h * 2];
                    float v1 = acc[i][nt][h * 2 + 1];
                    if (epi == 1) {
                        v0 += xr[col] + bs[col];
                        v1 += xr[col + 1] + bs[col + 1];
                    }
                    *(float2*)(crow + col) = make_float2(v0, v1);
                }
            }
        }
    }
#undef LOAD_STAGE
}

// ======================= launch =======================
extern "C" void kernel_launch(void* const* d_in, const int* in_sizes, int n_in,
                              void* d_out, int out_size) {
    const float* x   = (const float*)d_in[0];
    const float* tcx = (const float*)d_in[1];
    const float* tpw = (const float*)d_in[2];
    const float* tpb = (const float*)d_in[3];
    const float* gw  = (const float*)d_in[4];
    const float* eg  = (const float*)d_in[5];
    const float* eu  = (const float*)d_in[6];
    const float* ed  = (const float*)d_in[7];
    const float* sg  = (const float*)d_in[8];
    const float* su  = (const float*)d_in[9];
    const float* sd  = (const float*)d_in[10];
    float* out = (float*)d_out;

    cudaFuncSetAttribute(k_gemm, cudaFuncAttributeMaxDynamicSharedMemorySize, GEMM_SMEM);

    bf16 *xh, *xl, *tch, *tcl, *tpwTh, *tpwTl, *sgTh, *sgTl, *suTh, *suTl,
         *sdTh, *sdTl, *egTh, *egTl, *euTh, *euTl, *edTh, *edTl,
         *hsh, *hsl, *hh, *hl;
    float *xr, *gbuf, *ubuf, *eout, *listw;
    cudaGetSymbolAddress((void**)&xh, g_xh);   cudaGetSymbolAddress((void**)&xl, g_xl);
    cudaGetSymbolAddress((void**)&tch, g_tch); cudaGetSymbolAddress((void**)&tcl, g_tcl);
    cudaGetSymbolAddress((void**)&tpwTh, g_tpwT_h); cudaGetSymbolAddress((void**)&tpwTl, g_tpwT_l);
    cudaGetSymbolAddress((void**)&sgTh, g_sgT_h); cudaGetSymbolAddress((void**)&sgTl, g_sgT_l);
    cudaGetSymbolAddress((void**)&suTh, g_suT_h); cudaGetSymbolAddress((void**)&suTl, g_suT_l);
    cudaGetSymbolAddress((void**)&sdTh, g_sdT_h); cudaGetSymbolAddress((void**)&sdTl, g_sdT_l);
    cudaGetSymbolAddress((void**)&egTh, g_egT_h); cudaGetSymbolAddress((void**)&egTl, g_egT_l);
    cudaGetSymbolAddress((void**)&euTh, g_euT_h); cudaGetSymbolAddress((void**)&euTl, g_euT_l);
    cudaGetSymbolAddress((void**)&edTh, g_edT_h); cudaGetSymbolAddress((void**)&edTl, g_edT_l);
    cudaGetSymbolAddress((void**)&hsh, g_hsh); cudaGetSymbolAddress((void**)&hsl, g_hsl);
    cudaGetSymbolAddress((void**)&hh, g_hh);   cudaGetSymbolAddress((void**)&hl, g_hl);
    cudaGetSymbolAddress((void**)&xr, g_xr);
    cudaGetSymbolAddress((void**)&gbuf, g_gbuf); cudaGetSymbolAddress((void**)&ubuf, g_ubuf);
    cudaGetSymbolAddress((void**)&eout, g_eout);
    cudaGetSymbolAddress((void**)&listw, g_list_w);

    dim3 wb(32, 8);
    int n4 = T_TOK * HDIM / 4;

    // launch index 3 == shared-gate GEMM (ncu capture target)
    k_split<<<n4 / 256, 256>>>(x, xh, xl, n4);                                    // 0
    k_tsplit<<<dim3(IDIM/32, HDIM/32, 1), wb>>>(sg, sgTh, sgTl, HDIM, IDIM);      // 1
    k_tsplit<<<dim3(IDIM/32, HDIM/32, 1), wb>>>(su, suTh, suTl, HDIM, IDIM);      // 2
    k_gemm<<<dim3(IDIM/128, T_TOK/128, 1), 256, GEMM_SMEM>>>(                     // 3 <== ncu
        xh, xl, sgTh, sgTl, gbuf, HDIM, IDIM, T_TOK, 0, 0, 3, nullptr, nullptr);
    k_gemm<<<dim3(IDIM/128, T_TOK/128, 1), 256, GEMM_SMEM>>>(                     // 4
        xh, xl, suTh, suTl, ubuf, HDIM, IDIM, T_TOK, 0, 0, 3, nullptr, nullptr);
    k_init<<<1, 32>>>();                                                          // 5
    k_split<<<n4 / 256, 256>>>(tcx, tch, tcl, n4);                                // 6
    k_tsplit<<<dim3(HDIM/32, HDIM/32, 1), wb>>>(tpw, tpwTh, tpwTl, HDIM, HDIM);   // 7
    k_gemm<<<dim3(HDIM/128, T_TOK/128, 1), 256, GEMM_SMEM>>>(                     // 8 router
        tch, tcl, tpwTh, tpwTl, xr, HDIM, HDIM, T_TOK, 0, 1, 4, x, tpb);
    k_gate<<<T_TOK / 8, 256>>>(gw);                                               // 9
    k_offsets<<<1, 32>>>();                                                       // 10
    k_place<<<T_TOK / 256, 256>>>();                                              // 11
    k_silu<<<(T_TOK * IDIM / 4) / 256, 256>>>(gbuf, ubuf, hsh, hsl, nullptr,      // 12
                                              T_TOK * IDIM / 4);
    k_tsplit<<<dim3(HDIM/32, IDIM/32, 1), wb>>>(sd, sdTh, sdTl, IDIM, HDIM);      // 13
    k_gemm<<<dim3(HDIM/128, T_TOK/128, 1), 256, GEMM_SMEM>>>(                     // 14 shared down
        hsh, hsl, sdTh, sdTl, out, IDIM, HDIM, T_TOK, 0, 0, 3, nullptr, nullptr);
    k_tsplit<<<dim3(IDIM/32, HDIM/32, NEXP), wb>>>(eg, egTh, egTl, HDIM, IDIM);   // 15
    k_tsplit<<<dim3(IDIM/32, HDIM/32, NEXP), wb>>>(eu, euTh, euTl, HDIM, IDIM);   // 16
    k_tsplit<<<dim3(HDIM/32, IDIM/32, NEXP), wb>>>(ed, edTh, edTl, IDIM, HDIM);   // 17
    k_gemm<<<dim3(IDIM/128, SLOTS/128, NEXP), 256, GEMM_SMEM>>>(                  // 18 exp gate
        xh, xl, egTh, egTl, gbuf, HDIM, IDIM, 0, 1, 0, 3, nullptr, nullptr);
    k_gemm<<<dim3(IDIM/128, SLOTS/128, NEXP), 256, GEMM_SMEM>>>(                  // 19 exp up
        xh, xl, euTh, euTl, ubuf, HDIM, IDIM, 0, 1, 0, 3, nullptr, nullptr);
    k_silu<<<(SLOTS * IDIM / 4) / 256, 256>>>(gbuf, ubuf, hh, hl, listw,          // 20
                                              SLOTS * IDIM / 4);
    k_gemm<<<dim3(HDIM/128, SLOTS/128, NEXP), 256, GEMM_SMEM>>>(                  // 21 exp down
        hh, hl, edTh, edTl, eout, IDIM, HDIM, 0, 2, 0, 3, nullptr, nullptr);
    k_combine<<<(T_TOK * (HDIM / 4)) / 256, 256>>>(out);                          // 22
}

// round 8
// speedup vs baseline: 2.6127x; 1.1112x over previous
#include <cuda_runtime.h>
#include <cuda_bf16.h>
#include <stdint.h>
#include <math.h>

typedef __nv_bfloat16 bf16;
typedef unsigned long long u64;
typedef unsigned int u32;

#define T_TOK 4096
#define HDIM  1024
#define IDIM  2048
#define NEXP  8
#define SLOTS (2 * T_TOK)

// ======================= scratch (device globals) =======================
__device__ __align__(16) bf16 g_xh[(size_t)T_TOK * HDIM];
__device__ __align__(16) bf16 g_xl[(size_t)T_TOK * HDIM];
__device__ __align__(16) bf16 g_tch[(size_t)T_TOK * HDIM];
__device__ __align__(16) bf16 g_tcl[(size_t)T_TOK * HDIM];
__device__ __align__(16) bf16 g_tpwT_h[(size_t)HDIM * HDIM];
__device__ __align__(16) bf16 g_tpwT_l[(size_t)HDIM * HDIM];
__device__ __align__(16) bf16 g_sgT_h[(size_t)IDIM * HDIM];
__device__ __align__(16) bf16 g_sgT_l[(size_t)IDIM * HDIM];
__device__ __align__(16) bf16 g_suT_h[(size_t)IDIM * HDIM];
__device__ __align__(16) bf16 g_suT_l[(size_t)IDIM * HDIM];
__device__ __align__(16) bf16 g_sdT_h[(size_t)HDIM * IDIM];
__device__ __align__(16) bf16 g_sdT_l[(size_t)HDIM * IDIM];
__device__ __align__(16) bf16 g_egT_h[(size_t)NEXP * IDIM * HDIM];
__device__ __align__(16) bf16 g_egT_l[(size_t)NEXP * IDIM * HDIM];
__device__ __align__(16) bf16 g_euT_h[(size_t)NEXP * IDIM * HDIM];
__device__ __align__(16) bf16 g_euT_l[(size_t)NEXP * IDIM * HDIM];
__device__ __align__(16) bf16 g_edT_h[(size_t)NEXP * HDIM * IDIM];
__device__ __align__(16) bf16 g_edT_l[(size_t)NEXP * HDIM * IDIM];

__device__ float g_xr[(size_t)T_TOK * HDIM];
__device__ float g_gbuf[(size_t)SLOTS * IDIM];
__device__ float g_ubuf[(size_t)SLOTS * IDIM];
__device__ __align__(16) bf16 g_hsh[(size_t)T_TOK * IDIM];
__device__ __align__(16) bf16 g_hsl[(size_t)T_TOK * IDIM];
__device__ __align__(16) bf16 g_hh[(size_t)SLOTS * IDIM];
__device__ __align__(16) bf16 g_hl[(size_t)SLOTS * IDIM];
__device__ float g_eout[(size_t)SLOTS * HDIM];

__device__ int   g_tok_e[T_TOK * 2];
__device__ float g_tok_w[T_TOK * 2];
__device__ int   g_tok_slot[T_TOK * 2];
__device__ int   g_counts[NEXP];
__device__ int   g_offsets[NEXP];
__device__ int   g_cursor[NEXP];
__device__ int   g_list_tok[SLOTS];
__device__ float g_list_w[SLOTS];

// ======================= PTX helpers (sm_80-era, compute_103-safe) =======================
__device__ __forceinline__ u32 smem_u32(const void* p) {
    u32 a;
    asm("{ .reg .u64 t; cvta.to.shared.u64 t, %1; cvt.u32.u64 %0, t; }" : "=r"(a) : "l"(p));
    return a;
}
__device__ __forceinline__ void cpa16(u32 dst, const void* src) {
    asm volatile("cp.async.cg.shared.global [%0], [%1], 16;"
                 :: "r"(dst), "l"(src) : "memory");
}
__device__ __forceinline__ void cpa_commit() {
    asm volatile("cp.async.commit_group;" ::: "memory");
}
__device__ __forceinline__ void ldsm4(u32* r, u32 addr) {
    asm volatile("ldmatrix.sync.aligned.m8n8.x4.shared.b16 {%0,%1,%2,%3}, [%4];"
                 : "=r"(r[0]), "=r"(r[1]), "=r"(r[2]), "=r"(r[3]) : "r"(addr));
}
__device__ __forceinline__ void mma_bf16(float* c, const u32* a, u32 b0, u32 b1) {
    asm volatile("mma.sync.aligned.m16n8k16.row.col.f32.bf16.bf16.f32 "
                 "{%0,%1,%2,%3}, {%4,%5,%6,%7}, {%8,%9}, {%0,%1,%2,%3};"
                 : "+f"(c[0]), "+f"(c[1]), "+f"(c[2]), "+f"(c[3])
                 : "r"(a[0]), "r"(a[1]), "r"(a[2]), "r"(a[3]), "r"(b0), "r"(b1));
}

// ======================= small kernels =======================
__global__ void k_init() {
    int i = threadIdx.x;
    if (i < NEXP) { g_counts[i] = 0; g_cursor[i] = 0; }
}

__global__ void k_split(const float* __restrict__ S, bf16* __restrict__ H,
                        bf16* __restrict__ L, int n4) {
    int i = blockIdx.x * blockDim.x + threadIdx.x;
    if (i >= n4) return;
    float4 v = ((const float4*)S)[i];
    union { bf16 b[4]; ushort4 u; } uh, ul;
    float vv[4] = { v.x, v.y, v.z, v.w };
#pragma unroll
    for (int j = 0; j < 4; j++) {
        bf16 h = __float2bfloat16(vv[j]);
        uh.b[j] = h;
        ul.b[j] = __float2bfloat16(vv[j] - __bfloat162float(h));
    }
    ((ushort4*)H)[i] = uh.u;
    ((ushort4*)L)[i] = ul.u;
}

// transpose + split: W [K,N] fp32 -> Th/Tl [N,K] bf16 (z = expert)
__global__ void k_tsplit(const float* __restrict__ W, bf16* __restrict__ Th,
                         bf16* __restrict__ Tl, int K, int N) {
    size_t eo = (size_t)blockIdx.z * K * N;
    W += eo; Th += eo; Tl += eo;
    __shared__ float t[32][33];
    int k0 = blockIdx.y * 32, n0 = blockIdx.x * 32;
    int tx = threadIdx.x, ty = threadIdx.y;
#pragma unroll
    for (int q = 0; q < 4; q++)
        t[ty + 8 * q][tx] = W[(size_t)(k0 + ty + 8 * q) * N + n0 + tx];
    __syncthreads();
#pragma unroll
    for (int q = 0; q < 4; q++) {
        int n = ty + 8 * q;
        float v = t[tx][n];
        bf16 h = __float2bfloat16(v);
        bf16 l = __float2bfloat16(v - __bfloat162float(h));
        size_t o = (size_t)(n0 + n) * K + k0 + tx;
        Th[o] = h; Tl[o] = l;
    }
}

__global__ void k_gate(const float* __restrict__ gw) {
    int t = (blockIdx.x * blockDim.x + threadIdx.x) >> 5;
    int lane = threadIdx.x & 31;
    if (t >= T_TOK) return;
    const float* xr = g_xr + (size_t)t * HDIM;
    float acc[8] = {0.f,0.f,0.f,0.f,0.f,0.f,0.f,0.f};
    for (int h = lane; h < HDIM; h += 32) {
        float xv = xr[h];
        float4 w0 = *(const float4*)(gw + (size_t)h * 8);
        float4 w1 = *(const float4*)(gw + (size_t)h * 8 + 4);
        acc[0] += xv * w0.x; acc[1] += xv * w0.y; acc[2] += xv * w0.z; acc[3] += xv * w0.w;
        acc[4] += xv * w1.x; acc[5] += xv * w1.y; acc[6] += xv * w1.z; acc[7] += xv * w1.w;
    }
#pragma unroll
    for (int o = 16; o; o >>= 1)
#pragma unroll
        for (int e = 0; e < 8; e++) acc[e] += __shfl_down_sync(0xffffffffu, acc[e], o);
    if (lane == 0) {
        float mx = acc[0];
#pragma unroll
        for (int e = 1; e < 8; e++) mx = fmaxf(mx, acc[e]);
        float p[8]; float Z = 0.f;
#pragma unroll
        for (int e = 0; e < 8; e++) { p[e] = __expf(acc[e] - mx); Z += p[e]; }
        float rZ = 1.f / Z;
#pragma unroll
        for (int e = 0; e < 8; e++) p[e] *= rZ;
        int i0 = 0; float p0 = p[0];
#pragma unroll
        for (int e = 1; e < 8; e++) if (p[e] > p0) { p0 = p[e]; i0 = e; }
        int i1 = -1; float p1 = -1.f;
#pragma unroll
        for (int e = 0; e < 8; e++) if (e != i0 && p[e] > p1) { p1 = p[e]; i1 = e; }
        float s = 1.f / (p0 + p1 + 1e-5f);
        g_tok_e[2*t] = i0;     g_tok_w[2*t] = p0 * s;
        g_tok_e[2*t+1] = i1;   g_tok_w[2*t+1] = p1 * s;
        atomicAdd(&g_counts[i0], 1); atomicAdd(&g_counts[i1], 1);
    }
}

__global__ void k_offsets() {
    if (threadIdx.x == 0) {
        int s = 0;
        for (int e = 0; e < NEXP; e++) { g_offsets[e] = s; s += g_counts[e]; g_cursor[e] = 0; }
    }
}

__global__ void k_place() {
    int t = blockIdx.x * blockDim.x + threadIdx.x;
    if (t >= T_TOK) return;
#pragma unroll
    for (int k = 0; k < 2; k++) {
        int e = g_tok_e[2*t + k];
        int pos = g_offsets[e] + atomicAdd(&g_cursor[e], 1);
        g_list_tok[pos] = t;
        g_list_w[pos] = g_tok_w[2*t + k];
        g_tok_slot[2*t + k] = pos;
    }
}

__global__ void k_silu(const float* __restrict__ G, const float* __restrict__ U,
                       bf16* __restrict__ Hh, bf16* __restrict__ Hl,
                       const float* __restrict__ wrow, int n4) {
    int i = blockIdx.x * blockDim.x + threadIdx.x;
    if (i >= n4) return;
    int row = i / (IDIM / 4);
    float w = wrow ? wrow[row] : 1.0f;
    float4 g = ((const float4*)G)[i];
    float4 u = ((const float4*)U)[i];
    float gg[4] = { g.x, g.y, g.z, g.w };
    float uu[4] = { u.x, u.y, u.z, u.w };
    union { bf16 b[4]; ushort4 us; } uh, ul;
#pragma unroll
    for (int j = 0; j < 4; j++) {
        float gv = gg[j];
        float sig = 1.f / (1.f + __expf(-gv));
        float h = w * (gv * sig) * uu[j];
        bf16 hb = __float2bfloat16(h);
        uh.b[j] = hb;
        ul.b[j] = __float2bfloat16(h - __bfloat162float(hb));
    }
    ((ushort4*)Hh)[i] = uh.us;
    ((ushort4*)Hl)[i] = ul.us;
}

__global__ void k_combine(float* __restrict__ out) {
    int gid = blockIdx.x * blockDim.x + threadIdx.x;
    int t = gid / (HDIM / 4);
    int c = (gid % (HDIM / 4)) * 4;
    if (t >= T_TOK) return;
    int s0 = g_tok_slot[2*t], s1 = g_tok_slot[2*t+1];
    float4 o = *(const float4*)(out + (size_t)t * HDIM + c);
    float4 a = *(const float4*)(g_eout + (size_t)s0 * HDIM + c);
    float4 b = *(const float4*)(g_eout + (size_t)s1 * HDIM + c);
    o.x += a.x + b.x; o.y += a.y + b.y; o.z += a.z + b.z; o.w += a.w + b.w;
    *(float4*)(out + (size_t)t * HDIM + c) = o;
}

// ======================= bf16 HMMA GEMM (2-stage, 2 CTAs/SM) =======================
// C[M,N] = A @ B^T with bf16 hi/lo error compensation (3 or 4 passes).
// CTA 128x128, K-chunk 32, 2-stage cp.async pipeline, 8 warps (warp tile 64x32).
// Two __syncthreads per chunk for 2-stage buffer safety; occupancy 2 CTAs/SM.
// mode: 0 dense rows, 1 gathered (token list per expert), 2 slot rows (per expert)
// epi:  0 plain fp32 store, 1 router (+x +bias)
#define CH_K   32
#define ROWB   80
#define MATB   (128 * ROWB)          // 10240
#define STGB   (4 * MATB)            // 40960
#define GEMM_SMEM (2 * STGB)         // 81920

__global__ __launch_bounds__(256, 2) void k_gemm(
    const bf16* __restrict__ Ah, const bf16* __restrict__ Al,
    const bf16* __restrict__ Bh, const bf16* __restrict__ Bl,
    float* __restrict__ C, int Kdim, int Nld,
    int Mdense, int mode, int epi, int npass,
    const float* __restrict__ xadd, const float* __restrict__ bias)
{
    int cnt, off;
    if (mode == 0) { cnt = Mdense; off = 0; }
    else {
        int e = blockIdx.z;
        cnt = g_counts[e]; off = g_offsets[e];
        size_t wo = (size_t)e * Nld * Kdim;
        Bh += wo; Bl += wo;
    }
    const int m0 = blockIdx.y * 128;
    if (m0 >= cnt) return;
    const int n0 = blockIdx.x * 128;

    extern __shared__ char smem[];
    __shared__ int s_arow[128];
    const u32 sb = smem_u32(smem);
    const int tid = threadIdx.x;

    if (tid < 128) {
        int gr;
        if (mode == 0) gr = m0 + tid;
        else {
            int mr = m0 + tid; if (mr > cnt - 1) mr = cnt - 1;
            gr = (mode == 1) ? g_list_tok[off + mr] : (off + mr);
        }
        s_arow[tid] = gr;
    }
    __syncthreads();

    // loader: 4 matrices x 64 threads; each thread: 2 rows x 4 x 16B
    const int lmat = tid >> 6;
    const int lrow0 = (tid & 63) * 2;
    const bf16* lbase = (lmat == 0) ? Ah : (lmat == 1) ? Al : (lmat == 2) ? Bh : Bl;
    const bool lisA = lmat < 2;
    const int nc = Kdim / CH_K;

#define LOAD_STAGE(c) do {                                                   \
        int _k0 = (c) * CH_K;                                                \
        u32 _db = sb + ((c) & 1) * STGB + lmat * MATB;                       \
        _Pragma("unroll")                                                    \
        for (int _rr = 0; _rr < 2; _rr++) {                                  \
            int _row = lrow0 + _rr;                                          \
            int _gr = lisA ? s_arow[_row] : (n0 + _row);                     \
            const bf16* _p = lbase + (size_t)_gr * Kdim + _k0;               \
            u32 _d = _db + _row * ROWB;                                      \
            cpa16(_d,      _p);                                              \
            cpa16(_d + 16, _p + 8);                                          \
            cpa16(_d + 32, _p + 16);                                         \
            cpa16(_d + 48, _p + 24);                                         \
        }                                                                    \
    } while (0)

    float acc[4][4][4];
#pragma unroll
    for (int i = 0; i < 4; i++)
#pragma unroll
        for (int j = 0; j < 4; j++)
#pragma unroll
            for (int q = 0; q < 4; q++) acc[i][j][q] = 0.f;

    const int wid = tid >> 5, lane = tid & 31;
    const int wm = wid >> 2, wn = wid & 3;     // 2x4 warps -> 64x32 warp tile
    const int fr = lane & 15;                  // fragment row
    const int fk = ((lane >> 4) & 1) * 16;     // k 16B-half select

    LOAD_STAGE(0); cpa_commit();

    for (int c = 0; c < nc; c++) {
        // sync #1: all warps done consuming buffer (c+1)&1 from iteration c-1
        __syncthreads();
        if (c + 1 < nc) { LOAD_STAGE(c + 1); cpa_commit(); }
        if (c + 1 < nc) asm volatile("cp.async.wait_group 1;" ::: "memory");
        else            asm volatile("cp.async.wait_group 0;" ::: "memory");
        // sync #2: stage c data visible to all warps
        __syncthreads();

        const u32 ab = sb + (c & 1) * STGB;
        const u32 bb = ab + 2 * MATB;

#pragma unroll
        for (int kk = 0; kk < 2; kk++) {
            const int kb = kk * 32;
            u32 ahf[4][4], alf[4][4], bhf[2][4], blf[2][4];
#pragma unroll
            for (int i = 0; i < 4; i++) {
                u32 ad = ab + (wm * 64 + i * 16 + fr) * ROWB + kb + fk;
                ldsm4(ahf[i], ad);
                ldsm4(alf[i], ad + MATB);
            }
#pragma unroll
            for (int j = 0; j < 2; j++) {
                u32 bd = bb + (wn * 32 + j * 16 + fr) * ROWB + kb + fk;
                ldsm4(bhf[j], bd);
                ldsm4(blf[j], bd + MATB);
            }
#pragma unroll
            for (int i = 0; i < 4; i++)
#pragma unroll
                for (int nt = 0; nt < 4; nt++) {
                    int j = nt >> 1, t = nt & 1;
                    float* cc = acc[i][nt];
                    u32 b0h = bhf[j][t], b1h = bhf[j][t + 2];
                    u32 b0l = blf[j][t], b1l = blf[j][t + 2];
                    mma_bf16(cc, ahf[i], b0h, b1h);
                    mma_bf16(cc, ahf[i], b0l, b1l);
                    mma_bf16(cc, alf[i], b0h, b1h);
                    if (npass == 4) mma_bf16(cc, alf[i], b0l, b1l);
                }
        }
    }

    // epilogue: rows wm*64 + i*16 + lane/4 + {0,8}; cols wn*32 + nt*8 + (lane%4)*2 + {0,1}
#pragma unroll
    for (int i = 0; i < 4; i++) {
#pragma unroll
        for (int h = 0; h < 2; h++) {
            int lr = wm * 64 + i * 16 + (lane >> 2) + h * 8;
            if (m0 + lr < cnt) {
                int orow = (mode == 0 ? 0 : off) + m0 + lr;
                float* crow = C + (size_t)orow * Nld + n0 + wn * 32;
                const float* xr = (epi == 1) ? (xadd + (size_t)(m0 + lr) * HDIM + n0 + wn * 32) : nullptr;
                const float* bs = (epi == 1) ? (bias + n0 + wn * 32) : nullptr;
#pragma unroll
                for (int nt = 0; nt < 4; nt++) {
                    int col = nt * 8 + (lane & 3) * 2;
                    float v0 = acc[i][nt][h * 2];
                    float v1 = acc[i][nt][h * 2 + 1];
                    if (epi == 1) {
                        v0 += xr[col] + bs[col];
                        v1 += xr[col + 1] + bs[col + 1];
                    }
                    *(float2*)(crow + col) = make_float2(v0, v1);
                }
            }
        }
    }
#undef LOAD_STAGE
}

// ======================= launch =======================
extern "C" void kernel_launch(void* const* d_in, const int* in_sizes, int n_in,
                              void* d_out, int out_size) {
    const float* x   = (const float*)d_in[0];
    const float* tcx = (const float*)d_in[1];
    const float* tpw = (const float*)d_in[2];
    const float* tpb = (const float*)d_in[3];
    const float* gw  = (const float*)d_in[4];
    const float* eg  = (const float*)d_in[5];
    const float* eu  = (const float*)d_in[6];
    const float* ed  = (const float*)d_in[7];
    const float* sg  = (const float*)d_in[8];
    const float* su  = (const float*)d_in[9];
    const float* sd  = (const float*)d_in[10];
    float* out = (float*)d_out;

    cudaFuncSetAttribute(k_gemm, cudaFuncAttributeMaxDynamicSharedMemorySize, GEMM_SMEM);

    bf16 *xh, *xl, *tch, *tcl, *tpwTh, *tpwTl, *sgTh, *sgTl, *suTh, *suTl,
         *sdTh, *sdTl, *egTh, *egTl, *euTh, *euTl, *edTh, *edTl,
         *hsh, *hsl, *hh, *hl;
    float *xr, *gbuf, *ubuf, *eout, *listw;
    cudaGetSymbolAddress((void**)&xh, g_xh);   cudaGetSymbolAddress((void**)&xl, g_xl);
    cudaGetSymbolAddress((void**)&tch, g_tch); cudaGetSymbolAddress((void**)&tcl, g_tcl);
    cudaGetSymbolAddress((void**)&tpwTh, g_tpwT_h); cudaGetSymbolAddress((void**)&tpwTl, g_tpwT_l);
    cudaGetSymbolAddress((void**)&sgTh, g_sgT_h); cudaGetSymbolAddress((void**)&sgTl, g_sgT_l);
    cudaGetSymbolAddress((void**)&suTh, g_suT_h); cudaGetSymbolAddress((void**)&suTl, g_suT_l);
    cudaGetSymbolAddress((void**)&sdTh, g_sdT_h); cudaGetSymbolAddress((void**)&sdTl, g_sdT_l);
    cudaGetSymbolAddress((void**)&egTh, g_egT_h); cudaGetSymbolAddress((void**)&egTl, g_egT_l);
    cudaGetSymbolAddress((void**)&euTh, g_euT_h); cudaGetSymbolAddress((void**)&euTl, g_euT_l);
    cudaGetSymbolAddress((void**)&edTh, g_edT_h); cudaGetSymbolAddress((void**)&edTl, g_edT_l);
    cudaGetSymbolAddress((void**)&hsh, g_hsh); cudaGetSymbolAddress((void**)&hsl, g_hsl);
    cudaGetSymbolAddress((void**)&hh, g_hh);   cudaGetSymbolAddress((void**)&hl, g_hl);
    cudaGetSymbolAddress((void**)&xr, g_xr);
    cudaGetSymbolAddress((void**)&gbuf, g_gbuf); cudaGetSymbolAddress((void**)&ubuf, g_ubuf);
    cudaGetSymbolAddress((void**)&eout, g_eout);
    cudaGetSymbolAddress((void**)&listw, g_list_w);

    dim3 wb(32, 8);
    int n4 = T_TOK * HDIM / 4;

    // launch index 3 == shared-gate GEMM (ncu capture target)
    k_split<<<n4 / 256, 256>>>(x, xh, xl, n4);                                    // 0
    k_tsplit<<<dim3(IDIM/32, HDIM/32, 1), wb>>>(sg, sgTh, sgTl, HDIM, IDIM);      // 1
    k_tsplit<<<dim3(IDIM/32, HDIM/32, 1), wb>>>(su, suTh, suTl, HDIM, IDIM);      // 2
    k_gemm<<<dim3(IDIM/128, T_TOK/128, 1), 256, GEMM_SMEM>>>(                     // 3 <== ncu
        xh, xl, sgTh, sgTl, gbuf, HDIM, IDIM, T_TOK, 0, 0, 3, nullptr, nullptr);
    k_gemm<<<dim3(IDIM/128, T_TOK/128, 1), 256, GEMM_SMEM>>>(                     // 4
        xh, xl, suTh, suTl, ubuf, HDIM, IDIM, T_TOK, 0, 0, 3, nullptr, nullptr);
    k_init<<<1, 32>>>();                                                          // 5
    k_split<<<n4 / 256, 256>>>(tcx, tch, tcl, n4);                                // 6
    k_tsplit<<<dim3(HDIM/32, HDIM/32, 1), wb>>>(tpw, tpwTh, tpwTl, HDIM, HDIM);   // 7
    k_gemm<<<dim3(HDIM/128, T_TOK/128, 1), 256, GEMM_SMEM>>>(                     // 8 router
        tch, tcl, tpwTh, tpwTl, xr, HDIM, HDIM, T_TOK, 0, 1, 4, x, tpb);
    k_gate<<<T_TOK / 8, 256>>>(gw);                                               // 9
    k_offsets<<<1, 32>>>();                                                       // 10
    k_place<<<T_TOK / 256, 256>>>();                                              // 11
    k_silu<<<(T_TOK * IDIM / 4) / 256, 256>>>(gbuf, ubuf, hsh, hsl, nullptr,      // 12
                                              T_TOK * IDIM / 4);
    k_tsplit<<<dim3(HDIM/32, IDIM/32, 1), wb>>>(sd, sdTh, sdTl, IDIM, HDIM);      // 13
    k_gemm<<<dim3(HDIM/128, T_TOK/128, 1), 256, GEMM_SMEM>>>(                     // 14 shared down
        hsh, hsl, sdTh, sdTl, out, IDIM, HDIM, T_TOK, 0, 0, 3, nullptr, nullptr);
    k_tsplit<<<dim3(IDIM/32, HDIM/32, NEXP), wb>>>(eg, egTh, egTl, HDIM, IDIM);   // 15
    k_tsplit<<<dim3(IDIM/32, HDIM/32, NEXP), wb>>>(eu, euTh, euTl, HDIM, IDIM);   // 16
    k_tsplit<<<dim3(HDIM/32, IDIM/32, NEXP), wb>>>(ed, edTh, edTl, IDIM, HDIM);   // 17
    k_gemm<<<dim3(IDIM/128, SLOTS/128, NEXP), 256, GEMM_SMEM>>>(                  // 18 exp gate
        xh, xl, egTh, egTl, gbuf, HDIM, IDIM, 0, 1, 0, 3, nullptr, nullptr);
    k_gemm<<<dim3(IDIM/128, SLOTS/128, NEXP), 256, GEMM_SMEM>>>(                  // 19 exp up
        xh, xl, euTh, euTl, ubuf, HDIM, IDIM, 0, 1, 0, 3, nullptr, nullptr);
    k_silu<<<(SLOTS * IDIM / 4) / 256, 256>>>(gbuf, ubuf, hh, hl, listw,          // 20
                                              SLOTS * IDIM / 4);
    k_gemm<<<dim3(HDIM/128, SLOTS/128, NEXP), 256, GEMM_SMEM>>>(                  // 21 exp down
        hh, hl, edTh, edTl, eout, IDIM, HDIM, 0, 2, 0, 3, nullptr, nullptr);
    k_combine<<<(T_TOK * (HDIM / 4)) / 256, 256>>>(out);                          // 22
}